// round 14
// baseline (speedup 1.0000x reference)
#include <cuda_runtime.h>
#include <cuda_fp16.h>

// APRConv1x1, two K=32 HMMA GEMMs + select (R5/R8/R10 proven core).
// R14: even/odd point-interleaved MMA group pairs. Group E of pair j reads
// even points (slot parity 0) of stage rows 8j..8j+7, group O the odd points.
// Lane then holds 4 CONSECUTIVE points (16j+4t..+3) across the pair ->
// two direct STG.128 per pair: store wavefronts 256 -> 128 per tile with
// ZERO added indirection (the R9/R12 failure mode). ldmatrix slot algebra
// re-derived for 8-row groups; verified conflict-free. Select via ballot.

#define THREADS 128

__global__ __launch_bounds__(THREADS, 4)
void apr_mma10_kernel(const float* __restrict__ x,
                      const float* __restrict__ Wg,    // [16][16][4]
                      const float* __restrict__ bias,  // [16]
                      const int*   __restrict__ sidx,  // [P]
                      float* __restrict__ out,         // [B][16][N]
                      unsigned Nn, unsigned P)
{
    __shared__ __align__(16) char stage[4][8192];   // 64 rows x 128B per warp

    const int tid = threadIdx.x;
    const int wid = tid >> 5;
    const int l   = tid & 31;
    const int t   = l & 3;
    const int r   = l >> 2;

    // ---- once: weight A-fragments (k = 2i + j; W_h[o][2i+j] = Wg[o*64+4i+2h+j]) ----
    unsigned a[2][2][4];
#pragma unroll
    for (int h = 0; h < 2; h++)
#pragma unroll
        for (int ks = 0; ks < 2; ks++) {
            const int i0 = 8 * ks + t;
            const int i1 = 8 * ks + 4 + t;
            float2 w; __half2 hh;
            w = *(const float2*)(Wg + r * 64 + i0 * 4 + 2 * h);
            hh = __floats2half2_rn(w.x, w.y); a[h][ks][0] = *(unsigned*)&hh;
            w = *(const float2*)(Wg + (r + 8) * 64 + i0 * 4 + 2 * h);
            hh = __floats2half2_rn(w.x, w.y); a[h][ks][1] = *(unsigned*)&hh;
            w = *(const float2*)(Wg + r * 64 + i1 * 4 + 2 * h);
            hh = __floats2half2_rn(w.x, w.y); a[h][ks][2] = *(unsigned*)&hh;
            w = *(const float2*)(Wg + (r + 8) * 64 + i1 * 4 + 2 * h);
            hh = __floats2half2_rn(w.x, w.y); a[h][ks][3] = *(unsigned*)&hh;
        }
    const float br0 = __ldg(bias + r);
    const float br8 = __ldg(bias + r + 8);

    const unsigned wtiles = (P + 127) >> 7;
    const unsigned wstep  = (unsigned)gridDim.x * 4;
    unsigned wt = (unsigned)blockIdx.x * 4 + wid;
    if (wt >= wtiles) return;

    const unsigned sbase = (unsigned)__cvta_generic_to_shared(stage[wid]);

    // write-side (unchanged, verified): lane owns rows l and l+32
    const unsigned permw  = (((unsigned)l & 3u) << 1) | (((unsigned)l >> 2) & 1u);
    const unsigned waddr0 = sbase + ((unsigned)l << 7);
    // read-side for 8-row even/odd groups:
    //   address lane a = l&7, octet tt = l>>3, row = 8j + a,
    //   slotE = ((tt ^ (a&3))<<1) | ((a>>2)&1), slotO = slotE ^ 1
    const unsigned aL   = (unsigned)l & 7u;
    const unsigned ttL  = (unsigned)l >> 3;
    const unsigned slotE = (((ttL ^ (aL & 3u)) << 1) | ((aL >> 2) & 1u));
    const unsigned eaddr0 = sbase + (aL << 7) + (slotE << 4);
    const unsigned oaddr0 = sbase + (aL << 7) + ((slotE ^ 1u) << 4);
    // store row offsets
    const unsigned ro  = (unsigned)r * Nn;
    const unsigned ro8 = (unsigned)(r + 8) * Nn;

    // ---- prologue: load tile wt ----
    float2 fv0[16], fv1[16]; int2 sv0, sv1;
    {
        unsigned wtb = wt << 7; if (wtb + 128u > P) wtb = P - 128u;
        const unsigned b  = wtb >= Nn ? 1u : 0u;
        const unsigned n0 = wtb - b * Nn;
        const float* xp = x + (size_t)b * 16u * Nn + n0 + 2u * (unsigned)l;
#pragma unroll
        for (int i = 0; i < 16; i++) {
            fv0[i] = *reinterpret_cast<const float2*>(xp + (size_t)((unsigned)i * Nn));
            fv1[i] = *reinterpret_cast<const float2*>(xp + (size_t)((unsigned)i * Nn) + 64u);
        }
        sv0 = *reinterpret_cast<const int2*>(sidx + wtb + 2u * (unsigned)l);
        sv1 = *reinterpret_cast<const int2*>(sidx + wtb + 64u + 2u * (unsigned)l);
    }

    for (;;) {
        unsigned wtb = wt << 7; if (wtb + 128u > P) wtb = P - 128u;
        const unsigned b  = wtb >= Nn ? 1u : 0u;
        const unsigned n0 = wtb - b * Nn;
        float* fo = out + (size_t)b * 16u * Nn + n0;

        // current tile's stencil bits + warp-wide select masks
        const int se0 = sv0.x, so0 = sv0.y, se1 = sv1.x, so1 = sv1.y;
        const unsigned be0 = __ballot_sync(0xffffffffu, (se0 >> 1) & 1);
        const unsigned bo0 = __ballot_sync(0xffffffffu, (so0 >> 1) & 1);
        const unsigned be1 = __ballot_sync(0xffffffffu, (se1 >> 1) & 1);
        const unsigned bo1 = __ballot_sync(0xffffffffu, (so1 >> 1) & 1);

        // ---- pack + stage both halves (16x STS.128, conflict-free) ----
        {
            const unsigned she = ((unsigned)se0 & 1u) << 4;
            const unsigned sho = ((unsigned)so0 & 1u) << 4;
#pragma unroll
            for (int cc = 0; cc < 4; cc++) {
                unsigned e0, e1, e2, e3, o0, o1, o2, o3;
                e0 = (unsigned)__half_as_ushort(__float2half(fv0[4*cc+0].x)) << she;
                e1 = (unsigned)__half_as_ushort(__float2half(fv0[4*cc+1].x)) << she;
                e2 = (unsigned)__half_as_ushort(__float2half(fv0[4*cc+2].x)) << she;
                e3 = (unsigned)__half_as_ushort(__float2half(fv0[4*cc+3].x)) << she;
                o0 = (unsigned)__half_as_ushort(__float2half(fv0[4*cc+0].y)) << sho;
                o1 = (unsigned)__half_as_ushort(__float2half(fv0[4*cc+1].y)) << sho;
                o2 = (unsigned)__half_as_ushort(__float2half(fv0[4*cc+2].y)) << sho;
                o3 = (unsigned)__half_as_ushort(__float2half(fv0[4*cc+3].y)) << sho;
                const unsigned ae = waddr0 + ((((unsigned)(2*cc))     ^ permw) << 4);
                const unsigned ao = waddr0 + ((((unsigned)(2*cc + 1)) ^ permw) << 4);
                asm volatile("st.shared.v4.b32 [%0], {%1,%2,%3,%4};"
                             :: "r"(ae), "r"(e0), "r"(e1), "r"(e2), "r"(e3));
                asm volatile("st.shared.v4.b32 [%0], {%1,%2,%3,%4};"
                             :: "r"(ao), "r"(o0), "r"(o1), "r"(o2), "r"(o3));
            }
        }
        {
            const unsigned she = ((unsigned)se1 & 1u) << 4;
            const unsigned sho = ((unsigned)so1 & 1u) << 4;
#pragma unroll
            for (int cc = 0; cc < 4; cc++) {
                unsigned e0, e1, e2, e3, o0, o1, o2, o3;
                e0 = (unsigned)__half_as_ushort(__float2half(fv1[4*cc+0].x)) << she;
                e1 = (unsigned)__half_as_ushort(__float2half(fv1[4*cc+1].x)) << she;
                e2 = (unsigned)__half_as_ushort(__float2half(fv1[4*cc+2].x)) << she;
                e3 = (unsigned)__half_as_ushort(__float2half(fv1[4*cc+3].x)) << she;
                o0 = (unsigned)__half_as_ushort(__float2half(fv1[4*cc+0].y)) << sho;
                o1 = (unsigned)__half_as_ushort(__float2half(fv1[4*cc+1].y)) << sho;
                o2 = (unsigned)__half_as_ushort(__float2half(fv1[4*cc+2].y)) << sho;
                o3 = (unsigned)__half_as_ushort(__float2half(fv1[4*cc+3].y)) << sho;
                const unsigned ae = waddr0 + 4096u + ((((unsigned)(2*cc))     ^ permw) << 4);
                const unsigned ao = waddr0 + 4096u + ((((unsigned)(2*cc + 1)) ^ permw) << 4);
                asm volatile("st.shared.v4.b32 [%0], {%1,%2,%3,%4};"
                             :: "r"(ae), "r"(e0), "r"(e1), "r"(e2), "r"(e3));
                asm volatile("st.shared.v4.b32 [%0], {%1,%2,%3,%4};"
                             :: "r"(ao), "r"(o0), "r"(o1), "r"(o2), "r"(o3));
            }
        }

        // ---- prefetch next tile into the SAME registers (WAR after pack) ----
        const unsigned wtn = wt + wstep;
        const bool more = wtn < wtiles;
        if (more) {
            unsigned wtb2 = wtn << 7; if (wtb2 + 128u > P) wtb2 = P - 128u;
            const unsigned b2 = wtb2 >= Nn ? 1u : 0u;
            const unsigned n2 = wtb2 - b2 * Nn;
            const float* xp = x + (size_t)b2 * 16u * Nn + n2 + 2u * (unsigned)l;
#pragma unroll
            for (int i = 0; i < 16; i++) {
                fv0[i] = *reinterpret_cast<const float2*>(xp + (size_t)((unsigned)i * Nn));
                fv1[i] = *reinterpret_cast<const float2*>(xp + (size_t)((unsigned)i * Nn) + 64u);
            }
            sv0 = *reinterpret_cast<const int2*>(sidx + wtb2 + 2u * (unsigned)l);
            sv1 = *reinterpret_cast<const int2*>(sidx + wtb2 + 64u + 2u * (unsigned)l);
        }
        __syncwarp();

        // ---- compute: 8 pairs of (even, odd) groups over rows 8j..8j+7 ----
#pragma unroll
        for (int j = 0; j < 8; j++) {
            const unsigned jo = (unsigned)j << 10;          // 8 rows * 128B

            // --- even-point group: pts 16j + 2c ---
            unsigned b0, b1, b2, b3;
            asm volatile("ldmatrix.sync.aligned.m8n8.x4.shared.b16 {%0,%1,%2,%3}, [%4];"
                         : "=r"(b0), "=r"(b1), "=r"(b2), "=r"(b3) : "r"(eaddr0 + jo));
            float el0 = br0, el1 = br0, el2 = br8, el3 = br8;
            float eh0 = br0, eh1 = br0, eh2 = br8, eh3 = br8;
            asm volatile("mma.sync.aligned.m16n8k16.row.col.f32.f16.f16.f32 "
                "{%0,%1,%2,%3}, {%4,%5,%6,%7}, {%8,%9}, {%0,%1,%2,%3};"
                : "+f"(el0), "+f"(el1), "+f"(el2), "+f"(el3)
                : "r"(a[0][0][0]), "r"(a[0][0][1]), "r"(a[0][0][2]), "r"(a[0][0][3]),
                  "r"(b0), "r"(b1));
            asm volatile("mma.sync.aligned.m16n8k16.row.col.f32.f16.f16.f32 "
                "{%0,%1,%2,%3}, {%4,%5,%6,%7}, {%8,%9}, {%0,%1,%2,%3};"
                : "+f"(el0), "+f"(el1), "+f"(el2), "+f"(el3)
                : "r"(a[0][1][0]), "r"(a[0][1][1]), "r"(a[0][1][2]), "r"(a[0][1][3]),
                  "r"(b2), "r"(b3));
            asm volatile("mma.sync.aligned.m16n8k16.row.col.f32.f16.f16.f32 "
                "{%0,%1,%2,%3}, {%4,%5,%6,%7}, {%8,%9}, {%0,%1,%2,%3};"
                : "+f"(eh0), "+f"(eh1), "+f"(eh2), "+f"(eh3)
                : "r"(a[1][0][0]), "r"(a[1][0][1]), "r"(a[1][0][2]), "r"(a[1][0][3]),
                  "r"(b0), "r"(b1));
            asm volatile("mma.sync.aligned.m16n8k16.row.col.f32.f16.f16.f32 "
                "{%0,%1,%2,%3}, {%4,%5,%6,%7}, {%8,%9}, {%0,%1,%2,%3};"
                : "+f"(eh0), "+f"(eh1), "+f"(eh2), "+f"(eh3)
                : "r"(a[1][1][0]), "r"(a[1][1][1]), "r"(a[1][1][2]), "r"(a[1][1][3]),
                  "r"(b2), "r"(b3));

            // select bits: pts 16j+4t (+2) -> lanes lam, lam+1 of masks
            const unsigned lam = (unsigned)(8 * (j & 3) + 2 * t);
            const unsigned be  = (j < 4) ? be0 : be1;
            const unsigned bo  = (j < 4) ? bo0 : bo1;
            const float qe0 = ((be >> lam) & 1u)       ? eh0 : el0;   // pt 16j+4t,   row r
            const float qe1 = ((be >> (lam + 1)) & 1u) ? eh1 : el1;   // pt 16j+4t+2, row r
            const float qe2 = ((be >> lam) & 1u)       ? eh2 : el2;   // row r+8
            const float qe3 = ((be >> (lam + 1)) & 1u) ? eh3 : el3;

            // --- odd-point group: pts 16j + 2c + 1 ---
            asm volatile("ldmatrix.sync.aligned.m8n8.x4.shared.b16 {%0,%1,%2,%3}, [%4];"
                         : "=r"(b0), "=r"(b1), "=r"(b2), "=r"(b3) : "r"(oaddr0 + jo));
            float ol0 = br0, ol1 = br0, ol2 = br8, ol3 = br8;
            float oh0 = br0, oh1 = br0, oh2 = br8, oh3 = br8;
            asm volatile("mma.sync.aligned.m16n8k16.row.col.f32.f16.f16.f32 "
                "{%0,%1,%2,%3}, {%4,%5,%6,%7}, {%8,%9}, {%0,%1,%2,%3};"
                : "+f"(ol0), "+f"(ol1), "+f"(ol2), "+f"(ol3)
                : "r"(a[0][0][0]), "r"(a[0][0][1]), "r"(a[0][0][2]), "r"(a[0][0][3]),
                  "r"(b0), "r"(b1));
            asm volatile("mma.sync.aligned.m16n8k16.row.col.f32.f16.f16.f32 "
                "{%0,%1,%2,%3}, {%4,%5,%6,%7}, {%8,%9}, {%0,%1,%2,%3};"
                : "+f"(ol0), "+f"(ol1), "+f"(ol2), "+f"(ol3)
                : "r"(a[0][1][0]), "r"(a[0][1][1]), "r"(a[0][1][2]), "r"(a[0][1][3]),
                  "r"(b2), "r"(b3));
            asm volatile("mma.sync.aligned.m16n8k16.row.col.f32.f16.f16.f32 "
                "{%0,%1,%2,%3}, {%4,%5,%6,%7}, {%8,%9}, {%0,%1,%2,%3};"
                : "+f"(oh0), "+f"(oh1), "+f"(oh2), "+f"(oh3)
                : "r"(a[1][0][0]), "r"(a[1][0][1]), "r"(a[1][0][2]), "r"(a[1][0][3]),
                  "r"(b0), "r"(b1));
            asm volatile("mma.sync.aligned.m16n8k16.row.col.f32.f16.f16.f32 "
                "{%0,%1,%2,%3}, {%4,%5,%6,%7}, {%8,%9}, {%0,%1,%2,%3};"
                : "+f"(oh0), "+f"(oh1), "+f"(oh2), "+f"(oh3)
                : "r"(a[1][1][0]), "r"(a[1][1][1]), "r"(a[1][1][2]), "r"(a[1][1][3]),
                  "r"(b2), "r"(b3));

            const float qo0 = ((bo >> lam) & 1u)       ? oh0 : ol0;   // pt 16j+4t+1
            const float qo1 = ((bo >> (lam + 1)) & 1u) ? oh1 : ol1;   // pt 16j+4t+3
            const float qo2 = ((bo >> lam) & 1u)       ? oh2 : ol2;
            const float qo3 = ((bo >> (lam + 1)) & 1u) ? oh3 : ol3;

            // --- two direct STG.128: 4 consecutive points per row ---
            const unsigned p0 = (unsigned)(16 * j + 4 * t);
            *reinterpret_cast<float4*>(fo + ro  + p0) = make_float4(qe0, qo0, qe1, qo1);
            *reinterpret_cast<float4*>(fo + ro8 + p0) = make_float4(qe2, qo2, qe3, qo3);
        }
        __syncwarp();   // ldmatrix reads done before next iteration's STS

        if (!more) break;
        wt = wtn;
    }
}

extern "C" void kernel_launch(void* const* d_in, const int* in_sizes, int n_in,
                              void* d_out, int out_size)
{
    const float* x    = (const float*)d_in[0];   // [B, 16, N]
    const float* Wg   = (const float*)d_in[1];   // [16, 16, 4, 1, 1]
    const float* bias = (const float*)d_in[2];   // [16]
    const int*   sidx = (const int*)d_in[3];     // [B, N]

    float* out = (float*)d_out;

    const unsigned P  = (unsigned)in_sizes[3];   // B*N
    const unsigned Nn = P / 2;                   // B = 2

    const unsigned wtiles = (P + 127) / 128;
    unsigned blk = (wtiles + 3) / 4;
    if (blk > 592) blk = 592;                    // 4 CTAs x 148 SMs, persistent

    apr_mma10_kernel<<<blk, THREADS>>>(x, Wg, bias, sidx, out, Nn, P);
}